// round 6
// baseline (speedup 1.0000x reference)
#include <cuda_runtime.h>
#include <cuda_bf16.h>
#include <math.h>

#define F 128
#define MAXN 50000
#define MAXE 500000
#define MAXT (MAXE + MAXN)

// ---------------- scratch ----------------
__device__ __nv_bfloat162 g_xlb[(size_t)MAXN * 64];   // xl in bf16 (pairs)
__device__ __nv_bfloat162 g_xrb[(size_t)MAXN * 64];   // xr in bf16 (pairs)
__device__ int2     g_edge[MAXT];                     // (src,dst), or packed ushort2
__device__ float    g_p[MAXT];                        // exp(logit)
__device__ float    g_denom[MAXN];                    // sum_p -> 1/sum_p
__device__ float    g_acc[F];

// ---------------- edge normalization + init (inline dtype detect) -----------
__global__ void __launch_bounds__(256) convert_edges(
    const void* __restrict__ ei_raw, int nE, int nN, int pack16)
{
    __shared__ int s_is64;
    const long long* e64 = (const long long*)ei_raw;
    const int*       e32 = (const int*)ei_raw;

    if (threadIdx.x < 32) {
        const int lim = nE < 64 ? nE : 64;
        int bad = 0;
        for (int i = threadIdx.x; i < lim; i += 32) {
            long long v = e64[i];
            if (v < 0 || v >= (long long)nN) bad = 1;
        }
        unsigned m = __ballot_sync(0xffffffffu, bad);
        if (threadIdx.x == 0) s_is64 = (m == 0) ? 1 : 0;
    }
    __syncthreads();
    const int is64 = s_is64;

    const int total = nE + nN;
    const int gsz = gridDim.x * blockDim.x;
    ushort2* ep = reinterpret_cast<ushort2*>(g_edge);
    for (int i = blockIdx.x * blockDim.x + threadIdx.x; i < total; i += gsz) {
        int s, d;
        if (i < nE) {
            if (is64) { s = (int)e64[i]; d = (int)e64[nE + i]; }
            else      { s = e32[i];      d = e32[nE + i];      }
        } else {
            s = i - nE; d = s;
        }
        if (pack16) ep[i] = make_ushort2((unsigned short)s, (unsigned short)d);
        else        g_edge[i] = make_int2(s, d);
        if (i < nN) g_denom[i] = 0.f;
        if (i < F)  g_acc[i] = 0.f;
    }
}

// ---------------- tf32 tensor-core GEMM (split halves, persistent) ----------
__device__ __forceinline__ unsigned f2tf(float f) {
    unsigned r;
    asm("cvt.rna.tf32.f32 %0, %1;" : "=r"(r) : "f"(f));
    return r;
}
__device__ __forceinline__ void mma_tf32(float* c,
    unsigned a0, unsigned a1, unsigned a2, unsigned a3,
    unsigned b0, unsigned b1)
{
    asm volatile(
        "mma.sync.aligned.m16n8k8.row.col.f32.tf32.tf32.f32 "
        "{%0,%1,%2,%3}, {%4,%5,%6,%7}, {%8,%9}, {%0,%1,%2,%3};"
        : "+f"(c[0]), "+f"(c[1]), "+f"(c[2]), "+f"(c[3])
        : "r"(a0), "r"(a1), "r"(a2), "r"(a3), "r"(b0), "r"(b1));
}

#define WS_STRIDE 132
#define GEMM_SMEM (128 * WS_STRIDE * 4)   // 67584 B -> 2 blocks/SM
#define GEMM_GRID 296                     // even: block parity = W half

__global__ void __launch_bounds__(256, 2) gemm_tf32(
    const float* __restrict__ x,
    const float* __restrict__ Wl, const float* __restrict__ bl,
    const float* __restrict__ Wr, const float* __restrict__ br,
    int n, int ntiles)
{
    extern __shared__ unsigned Ws[];   // [128][132] tf32 words
    const int tid  = threadIdx.x;
    const int isL  = blockIdx.x & 1;
    const float* W    = isL ? Wl : Wr;
    const float* bias = isL ? bl : br;
    __nv_bfloat162* dst = isL ? g_xlb : g_xrb;

    // stage this half's W (128x128) as tf32, vectorized
    const float4* W4 = reinterpret_cast<const float4*>(W);
    for (int i = tid; i < 128 * 32; i += 256) {
        int k = i >> 5, q = i & 31;
        float4 v = W4[k * 32 + q];
        uint4 w = make_uint4(f2tf(v.x), f2tf(v.y), f2tf(v.z), f2tf(v.w));
        *reinterpret_cast<uint4*>(&Ws[k * WS_STRIDE + q * 4]) = w;
    }
    __syncthreads();

    const int warp = tid >> 5, lane = tid & 31;
    const int g  = lane >> 2;
    const int tk = lane & 3;
    const int nslots = gridDim.x >> 1;

    for (int tile = blockIdx.x >> 1; tile < ntiles; tile += nslots) {
        const int row0 = tile * 128 + warp * 16 + g;
        const int row1 = row0 + 8;
        const bool r0ok = row0 < n, r1ok = row1 < n;

        float c[16][4];
        #pragma unroll
        for (int t = 0; t < 16; t++) {
            c[t][0] = 0.f; c[t][1] = 0.f; c[t][2] = 0.f; c[t][3] = 0.f;
        }

        const float* x0 = x + (size_t)row0 * F;
        const float* x1 = x + (size_t)row1 * F;

        #pragma unroll
        for (int ks = 0; ks < 16; ks++) {
            const int kb = ks * 8;
            // raw fp32 bits: HW truncates to tf32 (<=2^-11 rel err)
            unsigned a0 = r0ok ? __float_as_uint(__ldg(x0 + kb + tk))     : 0u;
            unsigned a1 = r1ok ? __float_as_uint(__ldg(x1 + kb + tk))     : 0u;
            unsigned a2 = r0ok ? __float_as_uint(__ldg(x0 + kb + tk + 4)) : 0u;
            unsigned a3 = r1ok ? __float_as_uint(__ldg(x1 + kb + tk + 4)) : 0u;
            const unsigned* ws0 = Ws + (kb + tk) * WS_STRIDE + g;
            const unsigned* ws1 = ws0 + 4 * WS_STRIDE;
            #pragma unroll
            for (int nt = 0; nt < 16; nt++) {
                unsigned b0 = ws0[nt * 8];
                unsigned b1 = ws1[nt * 8];
                mma_tf32(c[nt], a0, a1, a2, a3, b0, b1);
            }
        }

        #pragma unroll
        for (int nt = 0; nt < 16; nt++) {
            int lc = nt * 8 + tk * 2;      // 0..126 within this half
            float b0 = __ldg(bias + lc);
            float b1 = __ldg(bias + lc + 1);
            if (r0ok) {
                __nv_bfloat162 h;
                h.x = __float2bfloat16(c[nt][0] + b0);
                h.y = __float2bfloat16(c[nt][1] + b1);
                dst[(size_t)row0 * 64 + (lc >> 1)] = h;
            }
            if (r1ok) {
                __nv_bfloat162 h;
                h.x = __float2bfloat16(c[nt][2] + b0);
                h.y = __float2bfloat16(c[nt][3] + b1);
                dst[(size_t)row1 * 64 + (lc >> 1)] = h;
            }
        }
    }
}

// ---------------- pass 1: logits + exp + denom (packed bf16 math) -----------
template<bool PACK16>
__global__ void __launch_bounds__(256) edge_pass1(
    const float* __restrict__ att, int total)
{
    const int lane = threadIdx.x & 31;
    const int sub  = lane & 15;
    const int half = lane >> 4;
    const int warp   = (blockIdx.x * blockDim.x + threadIdx.x) >> 5;
    const int nwarps = (gridDim.x * blockDim.x) >> 5;
    const int npairs = (total + 1) >> 1;

    const float4 a0 = reinterpret_cast<const float4*>(att)[sub * 2];
    const float4 a1 = reinterpret_cast<const float4*>(att)[sub * 2 + 1];
    const __nv_bfloat162 at0 = __floats2bfloat162_rn(a0.x, a0.y);
    const __nv_bfloat162 at1 = __floats2bfloat162_rn(a0.z, a0.w);
    const __nv_bfloat162 at2 = __floats2bfloat162_rn(a1.x, a1.y);
    const __nv_bfloat162 at3 = __floats2bfloat162_rn(a1.z, a1.w);
    const __nv_bfloat162 c02 = __float2bfloat162_rn(0.2f);
    const __nv_bfloat162 zero = __float2bfloat162_rn(0.f);

    const uint4* xl4 = reinterpret_cast<const uint4*>(g_xlb);
    const uint4* xr4 = reinterpret_cast<const uint4*>(g_xrb);
    const ushort2* ep = reinterpret_cast<const ushort2*>(g_edge);

    for (int pr = warp; pr < npairs; pr += nwarps) {
        const int e = pr * 2 + half;
        const bool ok = e < total;
        int s, d;
        if (PACK16) {
            ushort2 ed = ok ? ep[e] : make_ushort2(0, 0);
            s = ed.x; d = ed.y;
        } else {
            int2 ed = ok ? g_edge[e] : make_int2(0, 0);
            s = ed.x; d = ed.y;
        }

        uint4 up = xl4[(unsigned)s * 16u + sub];
        uint4 vp = xr4[(unsigned)d * 16u + sub];

        __nv_bfloat162 acc = zero;
        __nv_bfloat162 z;
        z = __hadd2(*(__nv_bfloat162*)&up.x, *(__nv_bfloat162*)&vp.x);
        z = __hmax2(z, __hmul2(z, c02));
        acc = __hfma2(at0, z, acc);
        z = __hadd2(*(__nv_bfloat162*)&up.y, *(__nv_bfloat162*)&vp.y);
        z = __hmax2(z, __hmul2(z, c02));
        acc = __hfma2(at1, z, acc);
        z = __hadd2(*(__nv_bfloat162*)&up.z, *(__nv_bfloat162*)&vp.z);
        z = __hmax2(z, __hmul2(z, c02));
        acc = __hfma2(at2, z, acc);
        z = __hadd2(*(__nv_bfloat162*)&up.w, *(__nv_bfloat162*)&vp.w);
        z = __hmax2(z, __hmul2(z, c02));
        acc = __hfma2(at3, z, acc);

        float2 s2 = __bfloat1622float2(acc);
        float sum = s2.x + s2.y;

        #pragma unroll
        for (int off = 8; off > 0; off >>= 1)
            sum += __shfl_xor_sync(0xffffffffu, sum, off);

        if (sub == 0 && ok) {
            float p = __expf(fminf(fmaxf(sum, -60.f), 60.f));
            g_p[e] = p;
            atomicAdd(&g_denom[d], p);
        }
    }
}

// ---------------- reciprocal of denom ----------------
__global__ void recip_kernel(int nN) {
    int i = blockIdx.x * blockDim.x + threadIdx.x;
    if (i < nN) g_denom[i] = 1.0f / g_denom[i];
}

// ---------------- pass 3: global weighted sum (bf16 gather, f32 acc) --------
template<bool PACK16>
__global__ void __launch_bounds__(256) edge_pass3(int total) {
    __shared__ float sacc[F];
    const int tid = threadIdx.x;
    if (tid < F) sacc[tid] = 0.f;
    __syncthreads();

    const int lane = tid & 31;
    const int sub  = lane & 15;
    const int half = lane >> 4;
    const int warp   = (blockIdx.x * blockDim.x + tid) >> 5;
    const int nwarps = (gridDim.x * blockDim.x) >> 5;
    const int npairs = (total + 1) >> 1;
    const uint4* xl4 = reinterpret_cast<const uint4*>(g_xlb);
    const ushort2* ep = reinterpret_cast<const ushort2*>(g_edge);

    float acc[8];
    #pragma unroll
    for (int k = 0; k < 8; k++) acc[k] = 0.f;

    for (int pr = warp; pr < npairs; pr += nwarps) {
        const int e = pr * 2 + half;
        const bool ok = e < total;
        int s, d;
        if (PACK16) {
            ushort2 ed = ok ? ep[e] : make_ushort2(0, 0);
            s = ed.x; d = ed.y;
        } else {
            int2 ed = ok ? g_edge[e] : make_int2(0, 0);
            s = ed.x; d = ed.y;
        }
        float w = ok ? g_p[e] * g_denom[d] : 0.f;

        uint4 up = xl4[(unsigned)s * 16u + sub];
        float2 f0 = __bfloat1622float2(*(__nv_bfloat162*)&up.x);
        float2 f1 = __bfloat1622float2(*(__nv_bfloat162*)&up.y);
        float2 f2 = __bfloat1622float2(*(__nv_bfloat162*)&up.z);
        float2 f3 = __bfloat1622float2(*(__nv_bfloat162*)&up.w);
        acc[0] += w * f0.x; acc[1] += w * f0.y;
        acc[2] += w * f1.x; acc[3] += w * f1.y;
        acc[4] += w * f2.x; acc[5] += w * f2.y;
        acc[6] += w * f3.x; acc[7] += w * f3.y;
    }

    #pragma unroll
    for (int k = 0; k < 8; k++)
        acc[k] += __shfl_xor_sync(0xffffffffu, acc[k], 16);
    if (half == 0) {
        #pragma unroll
        for (int k = 0; k < 8; k++)
            atomicAdd(&sacc[sub * 8 + k], acc[k]);
    }
    __syncthreads();
    if (tid < F) atomicAdd(&g_acc[tid], sacc[tid]);
}

// ---------------- finalize ----------------
__global__ void finalize(
    const float* __restrict__ bias1,
    const float* __restrict__ gamma, const float* __restrict__ beta,
    const float* __restrict__ mean,  const float* __restrict__ var,
    const float* __restrict__ Wc,    const float* __restrict__ bc,
    float* __restrict__ out, int nN)
{
    __shared__ float sg[F];
    __shared__ float sl[5];
    const int d = threadIdx.x;

    float gv = g_acc[d] / (float)nN + bias1[d];
    gv = (gv - mean[d]) * rsqrtf(var[d] + 1e-5f) * gamma[d] + beta[d];
    sg[d] = gv;
    __syncthreads();

    if (d < 5) {
        float s = bc[d];
        #pragma unroll 8
        for (int k = 0; k < F; k++) s += sg[k] * Wc[k * 5 + d];
        sl[d] = s;
    }
    __syncthreads();

    if (d == 0) {
        float mx = sl[0];
        #pragma unroll
        for (int c = 1; c < 5; c++) mx = fmaxf(mx, sl[c]);
        float e[5], sum = 0.f;
        #pragma unroll
        for (int c = 0; c < 5; c++) { e[c] = expf(sl[c] - mx); sum += e[c]; }
        #pragma unroll
        for (int c = 0; c < 5; c++) out[c] = e[c] / sum;
    }
}

// ---------------- launch ----------------
extern "C" void kernel_launch(void* const* d_in, const int* in_sizes, int n_in,
                              void* d_out, int out_size)
{
    const float* x     = (const float*)d_in[0];
    const void*  ei    = d_in[1];
    const float* Wl    = (const float*)d_in[2];
    const float* bl    = (const float*)d_in[3];
    const float* Wr    = (const float*)d_in[4];
    const float* br    = (const float*)d_in[5];
    const float* att   = (const float*)d_in[6];
    const float* bias1 = (const float*)d_in[7];
    const float* gamma = (const float*)d_in[8];
    const float* beta  = (const float*)d_in[9];
    const float* mean  = (const float*)d_in[10];
    const float* var   = (const float*)d_in[11];
    const float* Wc    = (const float*)d_in[12];
    const float* bc    = (const float*)d_in[13];
    float* out = (float*)d_out;

    const int nN = in_sizes[0] / F;
    const int nE = in_sizes[1] / 2;
    const int total = nE + nN;
    const int ntiles = (nN + 127) / 128;
    const int pack16 = (nN <= 65536) ? 1 : 0;

    static int smem_set = 0;
    if (!smem_set) {
        cudaFuncSetAttribute(gemm_tf32,
            cudaFuncAttributeMaxDynamicSharedMemorySize, GEMM_SMEM);
        smem_set = 1;
    }

    convert_edges<<<(total + 255) / 256, 256>>>(ei, nE, nN, pack16);
    gemm_tf32<<<GEMM_GRID, 256, GEMM_SMEM>>>(x, Wl, bl, Wr, br, nN, ntiles);
    if (pack16) {
        edge_pass1<true><<<2368, 256>>>(att, total);
        recip_kernel<<<(nN + 255) / 256, 256>>>(nN);
        edge_pass3<true><<<2368, 256>>>(total);
    } else {
        edge_pass1<false><<<2368, 256>>>(att, total);
        recip_kernel<<<(nN + 255) / 256, 256>>>(nN);
        edge_pass3<false><<<2368, 256>>>(total);
    }
    finalize<<<1, F>>>(bias1, gamma, beta, mean, var, Wc, bc, out, nN);
}

// round 7
// speedup vs baseline: 1.2294x; 1.2294x over previous
#include <cuda_runtime.h>
#include <cuda_bf16.h>
#include <math.h>

#define F 128
#define MAXN 50000
#define MAXE 500000
#define MAXT (MAXE + MAXN)

// ---------------- scratch ----------------
__device__ __nv_bfloat162 g_xlb[(size_t)MAXN * 64];   // xl in bf16 (pairs)
__device__ __nv_bfloat162 g_xrb[(size_t)MAXN * 64];   // xr in bf16 (pairs)
__device__ int2     g_edge[MAXT];                     // (src,dst) or packed ushort2
__device__ float    g_p[MAXT];                        // exp(logit)
__device__ float    g_denom[MAXN];                    // sum of p per dst
__device__ float    g_acc[F];
__device__ unsigned g_done;

// ---------------- edge normalization + init (inline dtype detect) -----------
__global__ void __launch_bounds__(256) convert_edges(
    const void* __restrict__ ei_raw, int nE, int nN, int pack16)
{
    __shared__ int s_is64;
    const long long* e64 = (const long long*)ei_raw;
    const int*       e32 = (const int*)ei_raw;

    if (threadIdx.x < 32) {
        const int lim = nE < 64 ? nE : 64;
        int bad = 0;
        for (int i = threadIdx.x; i < lim; i += 32) {
            long long v = e64[i];
            if (v < 0 || v >= (long long)nN) bad = 1;
        }
        unsigned m = __ballot_sync(0xffffffffu, bad);
        if (threadIdx.x == 0) s_is64 = (m == 0) ? 1 : 0;
    }
    __syncthreads();
    const int is64 = s_is64;

    if (blockIdx.x == 0 && threadIdx.x == 0) g_done = 0u;

    const int total = nE + nN;
    const int gsz = gridDim.x * blockDim.x;
    ushort2* ep = reinterpret_cast<ushort2*>(g_edge);
    for (int i = blockIdx.x * blockDim.x + threadIdx.x; i < total; i += gsz) {
        int s, d;
        if (i < nE) {
            if (is64) { s = (int)e64[i]; d = (int)e64[nE + i]; }
            else      { s = e32[i];      d = e32[nE + i];      }
        } else {
            s = i - nE; d = s;
        }
        if (pack16) ep[i] = make_ushort2((unsigned short)s, (unsigned short)d);
        else        g_edge[i] = make_int2(s, d);
        if (i < nN) g_denom[i] = 0.f;
        if (i < F)  g_acc[i] = 0.f;
    }
}

// ---------------- tf32 tensor-core GEMM (persistent, cp.async-staged A) -----
__device__ __forceinline__ unsigned f2tf(float f) {
    unsigned r;
    asm("cvt.rna.tf32.f32 %0, %1;" : "=r"(r) : "f"(f));
    return r;
}
__device__ __forceinline__ void mma_tf32(float* c,
    unsigned a0, unsigned a1, unsigned a2, unsigned a3,
    unsigned b0, unsigned b1)
{
    asm volatile(
        "mma.sync.aligned.m16n8k8.row.col.f32.tf32.tf32.f32 "
        "{%0,%1,%2,%3}, {%4,%5,%6,%7}, {%8,%9}, {%0,%1,%2,%3};"
        : "+f"(c[0]), "+f"(c[1]), "+f"(c[2]), "+f"(c[3])
        : "r"(a0), "r"(a1), "r"(a2), "r"(a3), "r"(b0), "r"(b1));
}
__device__ __forceinline__ void cp_async16(void* sdst, const void* gsrc) {
    unsigned sa = (unsigned)__cvta_generic_to_shared(sdst);
    asm volatile("cp.async.cg.shared.global [%0], [%1], 16;" :: "r"(sa), "l"(gsrc));
}

#define WS_STRIDE 264
#define XS_STRIDE 132
#define GEMM_SMEM (128 * WS_STRIDE * 4 + 128 * XS_STRIDE * 4)   // 202752 B
#define GEMM_GRID 148

__global__ void __launch_bounds__(256) gemm_tf32(
    const float* __restrict__ x,
    const float* __restrict__ Wl, const float* __restrict__ bl,
    const float* __restrict__ Wr, const float* __restrict__ br,
    int n, int ntiles)
{
    extern __shared__ unsigned char smraw[];
    unsigned* Ws = reinterpret_cast<unsigned*>(smraw);              // [128][264]
    float*    xs = reinterpret_cast<float*>(smraw + 128 * WS_STRIDE * 4); // [128][132]
    const int tid = threadIdx.x;

    // stage W = [Wl | Wr] as tf32, vectorized
    const float4* Wl4 = reinterpret_cast<const float4*>(Wl);
    const float4* Wr4 = reinterpret_cast<const float4*>(Wr);
    for (int i = tid; i < 128 * 64; i += 256) {
        int k = i >> 6, q = i & 63;
        float4 v = (q < 32) ? Wl4[k * 32 + q] : Wr4[k * 32 + (q - 32)];
        uint4 w = make_uint4(f2tf(v.x), f2tf(v.y), f2tf(v.z), f2tf(v.w));
        *reinterpret_cast<uint4*>(&Ws[k * WS_STRIDE + q * 4]) = w;
    }

    const int warp = tid >> 5, lane = tid & 31;
    const int g  = lane >> 2;
    const int tk = lane & 3;

    __syncthreads();

    for (int tile = blockIdx.x; tile < ntiles; tile += gridDim.x) {
        // bulk-load x tile (128 rows x 128 f32) into padded smem
        #pragma unroll
        for (int j = 0; j < 16; j++) {
            int id = tid + j * 256;
            int r = id >> 5, q = id & 31;
            int grow = tile * 128 + r;
            if (grow < n)
                cp_async16(&xs[r * XS_STRIDE + q * 4],
                           x + (size_t)grow * F + q * 4);
        }
        asm volatile("cp.async.commit_group;");
        asm volatile("cp.async.wait_group 0;");
        __syncthreads();

        const int row0 = tile * 128 + warp * 16 + g;
        const int row1 = row0 + 8;
        const bool r0ok = row0 < n, r1ok = row1 < n;

        float c[32][4];
        #pragma unroll
        for (int t = 0; t < 32; t++) {
            c[t][0] = 0.f; c[t][1] = 0.f; c[t][2] = 0.f; c[t][3] = 0.f;
        }

        const float* x0s = xs + (warp * 16 + g) * XS_STRIDE;
        const float* x1s = x0s + 8 * XS_STRIDE;

        #pragma unroll
        for (int ks = 0; ks < 16; ks++) {
            const int kb = ks * 8;
            unsigned a0 = __float_as_uint(x0s[kb + tk]);
            unsigned a1 = __float_as_uint(x1s[kb + tk]);
            unsigned a2 = __float_as_uint(x0s[kb + tk + 4]);
            unsigned a3 = __float_as_uint(x1s[kb + tk + 4]);
            const unsigned* ws0 = Ws + (kb + tk) * WS_STRIDE + g;
            const unsigned* ws1 = ws0 + 4 * WS_STRIDE;
            #pragma unroll
            for (int nt = 0; nt < 32; nt++) {
                unsigned b0 = ws0[nt * 8];
                unsigned b1 = ws1[nt * 8];
                mma_tf32(c[nt], a0, a1, a2, a3, b0, b1);
            }
        }

        #pragma unroll
        for (int nt = 0; nt < 32; nt++) {
            int col = nt * 8 + tk * 2;
            bool isL = (col < 128);
            int lc = isL ? col : col - 128;
            float b0 = __ldg((isL ? bl : br) + lc);
            float b1 = __ldg((isL ? bl : br) + lc + 1);
            __nv_bfloat162* dst = isL ? g_xlb : g_xrb;
            if (r0ok) {
                __nv_bfloat162 h;
                h.x = __float2bfloat16(c[nt][0] + b0);
                h.y = __float2bfloat16(c[nt][1] + b1);
                dst[(size_t)row0 * 64 + (lc >> 1)] = h;
            }
            if (r1ok) {
                __nv_bfloat162 h;
                h.x = __float2bfloat16(c[nt][2] + b0);
                h.y = __float2bfloat16(c[nt][3] + b1);
                dst[(size_t)row1 * 64 + (lc >> 1)] = h;
            }
        }
        __syncthreads();   // xs reuse safety for next tile
    }
}

// ---------------- pass 1: logits + exp + denom (2 edges per half-warp) ------
template<bool PACK16>
__global__ void __launch_bounds__(256) edge_pass1(
    const float* __restrict__ att, int total)
{
    const int lane = threadIdx.x & 31;
    const int sub  = lane & 15;
    const int half = lane >> 4;
    const int warp   = (blockIdx.x * blockDim.x + threadIdx.x) >> 5;
    const int nwarps = (gridDim.x * blockDim.x) >> 5;

    const float4 a0 = reinterpret_cast<const float4*>(att)[sub * 2];
    const float4 a1 = reinterpret_cast<const float4*>(att)[sub * 2 + 1];
    const __nv_bfloat162 at0 = __floats2bfloat162_rn(a0.x, a0.y);
    const __nv_bfloat162 at1 = __floats2bfloat162_rn(a0.z, a0.w);
    const __nv_bfloat162 at2 = __floats2bfloat162_rn(a1.x, a1.y);
    const __nv_bfloat162 at3 = __floats2bfloat162_rn(a1.z, a1.w);
    const __nv_bfloat162 c02 = __float2bfloat162_rn(0.2f);

    const uint4* xl4 = reinterpret_cast<const uint4*>(g_xlb);
    const uint4* xr4 = reinterpret_cast<const uint4*>(g_xrb);
    const ushort2* ep = reinterpret_cast<const ushort2*>(g_edge);

    for (int base = warp * 4; base < total; base += nwarps * 4) {
        const int e0 = base + half * 2;
        const int e1 = e0 + 1;
        const bool ok0 = e0 < total, ok1 = e1 < total;

        int s0 = 0, d0 = 0, s1 = 0, d1 = 0;
        if (PACK16) {
            if (ok1) {
                uint2 m = *reinterpret_cast<const uint2*>(&ep[e0]);
                s0 = m.x & 0xffffu; d0 = m.x >> 16;
                s1 = m.y & 0xffffu; d1 = m.y >> 16;
            } else if (ok0) {
                ushort2 m0 = ep[e0]; s0 = m0.x; d0 = m0.y;
            }
        } else {
            if (ok0) { int2 m0 = g_edge[e0]; s0 = m0.x; d0 = m0.y; }
            if (ok1) { int2 m1 = g_edge[e1]; s1 = m1.x; d1 = m1.y; }
        }

        uint4 up0 = xl4[(unsigned)s0 * 16u + sub];
        uint4 vp0 = xr4[(unsigned)d0 * 16u + sub];
        uint4 up1 = xl4[(unsigned)s1 * 16u + sub];
        uint4 vp1 = xr4[(unsigned)d1 * 16u + sub];

        __nv_bfloat162 acc0 = __float2bfloat162_rn(0.f);
        __nv_bfloat162 acc1 = __float2bfloat162_rn(0.f);
        __nv_bfloat162 z;
        z = __hadd2(*(__nv_bfloat162*)&up0.x, *(__nv_bfloat162*)&vp0.x);
        z = __hmax2(z, __hmul2(z, c02)); acc0 = __hfma2(at0, z, acc0);
        z = __hadd2(*(__nv_bfloat162*)&up0.y, *(__nv_bfloat162*)&vp0.y);
        z = __hmax2(z, __hmul2(z, c02)); acc0 = __hfma2(at1, z, acc0);
        z = __hadd2(*(__nv_bfloat162*)&up0.z, *(__nv_bfloat162*)&vp0.z);
        z = __hmax2(z, __hmul2(z, c02)); acc0 = __hfma2(at2, z, acc0);
        z = __hadd2(*(__nv_bfloat162*)&up0.w, *(__nv_bfloat162*)&vp0.w);
        z = __hmax2(z, __hmul2(z, c02)); acc0 = __hfma2(at3, z, acc0);

        z = __hadd2(*(__nv_bfloat162*)&up1.x, *(__nv_bfloat162*)&vp1.x);
        z = __hmax2(z, __hmul2(z, c02)); acc1 = __hfma2(at0, z, acc1);
        z = __hadd2(*(__nv_bfloat162*)&up1.y, *(__nv_bfloat162*)&vp1.y);
        z = __hmax2(z, __hmul2(z, c02)); acc1 = __hfma2(at1, z, acc1);
        z = __hadd2(*(__nv_bfloat162*)&up1.z, *(__nv_bfloat162*)&vp1.z);
        z = __hmax2(z, __hmul2(z, c02)); acc1 = __hfma2(at2, z, acc1);
        z = __hadd2(*(__nv_bfloat162*)&up1.w, *(__nv_bfloat162*)&vp1.w);
        z = __hmax2(z, __hmul2(z, c02)); acc1 = __hfma2(at3, z, acc1);

        float2 f0 = __bfloat1622float2(acc0);
        float2 f1 = __bfloat1622float2(acc1);
        float sum0 = f0.x + f0.y;
        float sum1 = f1.x + f1.y;

        #pragma unroll
        for (int off = 8; off > 0; off >>= 1) {
            sum0 += __shfl_xor_sync(0xffffffffu, sum0, off);
            sum1 += __shfl_xor_sync(0xffffffffu, sum1, off);
        }

        if (sub == 0) {
            float p0 = __expf(fminf(fmaxf(sum0, -60.f), 60.f));
            float p1 = __expf(fminf(fmaxf(sum1, -60.f), 60.f));
            if (ok1) {
                *reinterpret_cast<float2*>(&g_p[e0]) = make_float2(p0, p1);
                atomicAdd(&g_denom[d0], p0);
                atomicAdd(&g_denom[d1], p1);
            } else if (ok0) {
                g_p[e0] = p0;
                atomicAdd(&g_denom[d0], p0);
            }
        }
    }
}

// ---------------- pass 3 + fused finalize ----------------
template<bool PACK16>
__global__ void __launch_bounds__(256) edge_pass3(
    int total, int nN,
    const float* __restrict__ bias1,
    const float* __restrict__ gamma, const float* __restrict__ beta,
    const float* __restrict__ mean,  const float* __restrict__ var,
    const float* __restrict__ Wc,    const float* __restrict__ bc,
    float* __restrict__ out)
{
    __shared__ float sacc[F];
    __shared__ int s_last;
    const int tid = threadIdx.x;
    if (tid < F) sacc[tid] = 0.f;
    __syncthreads();

    const int lane = tid & 31;
    const int sub  = lane & 15;
    const int half = lane >> 4;
    const int warp   = (blockIdx.x * blockDim.x + tid) >> 5;
    const int nwarps = (gridDim.x * blockDim.x) >> 5;
    const uint4* xl4 = reinterpret_cast<const uint4*>(g_xlb);
    const ushort2* ep = reinterpret_cast<const ushort2*>(g_edge);

    float acc[8];
    #pragma unroll
    for (int k = 0; k < 8; k++) acc[k] = 0.f;

    for (int base = warp * 4; base < total; base += nwarps * 4) {
        const int e0 = base + half * 2;
        const int e1 = e0 + 1;
        const bool ok0 = e0 < total, ok1 = e1 < total;

        int s0 = 0, d0 = 0, s1 = 0, d1 = 0;
        if (PACK16) {
            if (ok1) {
                uint2 m = *reinterpret_cast<const uint2*>(&ep[e0]);
                s0 = m.x & 0xffffu; d0 = m.x >> 16;
                s1 = m.y & 0xffffu; d1 = m.y >> 16;
            } else if (ok0) {
                ushort2 m0 = ep[e0]; s0 = m0.x; d0 = m0.y;
            }
        } else {
            if (ok0) { int2 m0 = g_edge[e0]; s0 = m0.x; d0 = m0.y; }
            if (ok1) { int2 m1 = g_edge[e1]; s1 = m1.x; d1 = m1.y; }
        }

        float w0 = 0.f, w1 = 0.f;
        if (ok1) {
            float2 pv = *reinterpret_cast<const float2*>(&g_p[e0]);
            w0 = __fdividef(pv.x, g_denom[d0]);
            w1 = __fdividef(pv.y, g_denom[d1]);
        } else if (ok0) {
            w0 = __fdividef(g_p[e0], g_denom[d0]);
        }

        uint4 up0 = xl4[(unsigned)s0 * 16u + sub];
        uint4 up1 = xl4[(unsigned)s1 * 16u + sub];

        float2 f0 = __bfloat1622float2(*(__nv_bfloat162*)&up0.x);
        float2 f1 = __bfloat1622float2(*(__nv_bfloat162*)&up0.y);
        float2 f2 = __bfloat1622float2(*(__nv_bfloat162*)&up0.z);
        float2 f3 = __bfloat1622float2(*(__nv_bfloat162*)&up0.w);
        float2 h0 = __bfloat1622float2(*(__nv_bfloat162*)&up1.x);
        float2 h1 = __bfloat1622float2(*(__nv_bfloat162*)&up1.y);
        float2 h2 = __bfloat1622float2(*(__nv_bfloat162*)&up1.z);
        float2 h3 = __bfloat1622float2(*(__nv_bfloat162*)&up1.w);

        acc[0] += w0 * f0.x + w1 * h0.x;  acc[1] += w0 * f0.y + w1 * h0.y;
        acc[2] += w0 * f1.x + w1 * h1.x;  acc[3] += w0 * f1.y + w1 * h1.y;
        acc[4] += w0 * f2.x + w1 * h2.x;  acc[5] += w0 * f2.y + w1 * h2.y;
        acc[6] += w0 * f3.x + w1 * h3.x;  acc[7] += w0 * f3.y + w1 * h3.y;
    }

    #pragma unroll
    for (int k = 0; k < 8; k++)
        acc[k] += __shfl_xor_sync(0xffffffffu, acc[k], 16);
    if (half == 0) {
        #pragma unroll
        for (int k = 0; k < 8; k++)
            atomicAdd(&sacc[sub * 8 + k], acc[k]);
    }
    __syncthreads();
    if (tid < F) atomicAdd(&g_acc[tid], sacc[tid]);

    // ---- last block runs finalize ----
    __syncthreads();
    if (tid == 0) {
        __threadfence();
        unsigned v = atomicAdd(&g_done, 1u);
        s_last = (v == gridDim.x - 1) ? 1 : 0;
    }
    __syncthreads();
    if (!s_last) return;

    __shared__ float sg[F];
    __shared__ float sl[5];
    if (tid < F) {
        float gv = atomicAdd(&g_acc[tid], 0.f);   // L2-coherent read
        gv = gv / (float)nN + bias1[tid];
        gv = (gv - mean[tid]) * rsqrtf(var[tid] + 1e-5f) * gamma[tid] + beta[tid];
        sg[tid] = gv;
    }
    __syncthreads();
    if (tid < 5) {
        float s = bc[tid];
        #pragma unroll 8
        for (int k = 0; k < F; k++) s += sg[k] * Wc[k * 5 + tid];
        sl[tid] = s;
    }
    __syncthreads();
    if (tid == 0) {
        float mx = sl[0];
        #pragma unroll
        for (int c = 1; c < 5; c++) mx = fmaxf(mx, sl[c]);
        float e[5], sum = 0.f;
        #pragma unroll
        for (int c = 0; c < 5; c++) { e[c] = expf(sl[c] - mx); sum += e[c]; }
        #pragma unroll
        for (int c = 0; c < 5; c++) out[c] = e[c] / sum;
    }
}

// ---------------- launch ----------------
extern "C" void kernel_launch(void* const* d_in, const int* in_sizes, int n_in,
                              void* d_out, int out_size)
{
    const float* x     = (const float*)d_in[0];
    const void*  ei    = d_in[1];
    const float* Wl    = (const float*)d_in[2];
    const float* bl    = (const float*)d_in[3];
    const float* Wr    = (const float*)d_in[4];
    const float* br    = (const float*)d_in[5];
    const float* att   = (const float*)d_in[6];
    const float* bias1 = (const float*)d_in[7];
    const float* gamma = (const float*)d_in[8];
    const float* beta  = (const float*)d_in[9];
    const float* mean  = (const float*)d_in[10];
    const float* var   = (const float*)d_in[11];
    const float* Wc    = (const float*)d_in[12];
    const float* bc    = (const float*)d_in[13];
    float* out = (float*)d_out;

    const int nN = in_sizes[0] / F;
    const int nE = in_sizes[1] / 2;
    const int total = nE + nN;
    const int ntiles = (nN + 127) / 128;
    const int pack16 = (nN <= 65536) ? 1 : 0;

    static int smem_set = 0;
    if (!smem_set) {
        cudaFuncSetAttribute(gemm_tf32,
            cudaFuncAttributeMaxDynamicSharedMemorySize, GEMM_SMEM);
        smem_set = 1;
    }

    convert_edges<<<(total + 255) / 256, 256>>>(ei, nE, nN, pack16);
    gemm_tf32<<<GEMM_GRID, 256, GEMM_SMEM>>>(x, Wl, bl, Wr, br, nN, ntiles);
    if (pack16) {
        edge_pass1<true><<<2368, 256>>>(att, total);
        edge_pass3<true><<<2368, 256>>>(total, nN, bias1, gamma, beta,
                                        mean, var, Wc, bc, out);
    } else {
        edge_pass1<false><<<2368, 256>>>(att, total);
        edge_pass3<false><<<2368, 256>>>(total, nN, bias1, gamma, beta,
                                         mean, var, Wc, bc, out);
    }
}

// round 8
// speedup vs baseline: 1.4050x; 1.1428x over previous
#include <cuda_runtime.h>
#include <cuda_bf16.h>
#include <math.h>

#define F 128
#define MAXN 50000
#define MAXE 500000
#define MAXT (MAXE + MAXN)

// ---------------- scratch ----------------
__device__ __nv_bfloat162 g_xlb[(size_t)MAXN * 64];   // xl in bf16 (pairs)
__device__ __nv_bfloat162 g_xrb[(size_t)MAXN * 64];   // xr in bf16 (pairs)
__device__ int2     g_edge[MAXT];                     // (src,dst) or packed ushort2
__device__ float    g_p[MAXT];                        // exp(logit)
__device__ float    g_denom[MAXN];                    // sum of p per dst
__device__ float    g_coef[MAXN];                     // sum of w per src
__device__ float    g_acc[F];
__device__ unsigned g_done;

// ---------------- edge normalization + init (inline dtype detect) -----------
__global__ void __launch_bounds__(256) convert_edges(
    const void* __restrict__ ei_raw, int nE, int nN, int pack16)
{
    __shared__ int s_is64;
    const long long* e64 = (const long long*)ei_raw;
    const int*       e32 = (const int*)ei_raw;

    if (threadIdx.x < 32) {
        const int lim = nE < 64 ? nE : 64;
        int bad = 0;
        for (int i = threadIdx.x; i < lim; i += 32) {
            long long v = e64[i];
            if (v < 0 || v >= (long long)nN) bad = 1;
        }
        unsigned m = __ballot_sync(0xffffffffu, bad);
        if (threadIdx.x == 0) s_is64 = (m == 0) ? 1 : 0;
    }
    __syncthreads();
    const int is64 = s_is64;

    if (blockIdx.x == 0 && threadIdx.x == 0) g_done = 0u;

    const int total = nE + nN;
    const int gsz = gridDim.x * blockDim.x;
    ushort2* ep = reinterpret_cast<ushort2*>(g_edge);
    for (int i = blockIdx.x * blockDim.x + threadIdx.x; i < total; i += gsz) {
        int s, d;
        if (i < nE) {
            if (is64) { s = (int)e64[i]; d = (int)e64[nE + i]; }
            else      { s = e32[i];      d = e32[nE + i];      }
        } else {
            s = i - nE; d = s;
        }
        if (pack16) ep[i] = make_ushort2((unsigned short)s, (unsigned short)d);
        else        g_edge[i] = make_int2(s, d);
        if (i < nN) { g_denom[i] = 0.f; g_coef[i] = 0.f; }
        if (i < F)  g_acc[i] = 0.f;
    }
}

// ---------------- tf32 tensor-core GEMM (persistent, cp.async-staged A) -----
__device__ __forceinline__ unsigned f2tf(float f) {
    unsigned r;
    asm("cvt.rna.tf32.f32 %0, %1;" : "=r"(r) : "f"(f));
    return r;
}
__device__ __forceinline__ void mma_tf32(float* c,
    unsigned a0, unsigned a1, unsigned a2, unsigned a3,
    unsigned b0, unsigned b1)
{
    asm volatile(
        "mma.sync.aligned.m16n8k8.row.col.f32.tf32.tf32.f32 "
        "{%0,%1,%2,%3}, {%4,%5,%6,%7}, {%8,%9}, {%0,%1,%2,%3};"
        : "+f"(c[0]), "+f"(c[1]), "+f"(c[2]), "+f"(c[3])
        : "r"(a0), "r"(a1), "r"(a2), "r"(a3), "r"(b0), "r"(b1));
}
__device__ __forceinline__ void cp_async16(void* sdst, const void* gsrc) {
    unsigned sa = (unsigned)__cvta_generic_to_shared(sdst);
    asm volatile("cp.async.cg.shared.global [%0], [%1], 16;" :: "r"(sa), "l"(gsrc));
}

#define WS_STRIDE 264
#define XS_STRIDE 132
#define GEMM_SMEM (128 * WS_STRIDE * 4 + 128 * XS_STRIDE * 4)   // 202752 B
#define GEMM_GRID 148

__global__ void __launch_bounds__(256) gemm_tf32(
    const float* __restrict__ x,
    const float* __restrict__ Wl, const float* __restrict__ bl,
    const float* __restrict__ Wr, const float* __restrict__ br,
    int n, int ntiles)
{
    extern __shared__ unsigned char smraw[];
    unsigned* Ws = reinterpret_cast<unsigned*>(smraw);              // [128][264]
    float*    xs = reinterpret_cast<float*>(smraw + 128 * WS_STRIDE * 4); // [128][132]
    const int tid = threadIdx.x;

    const float4* Wl4 = reinterpret_cast<const float4*>(Wl);
    const float4* Wr4 = reinterpret_cast<const float4*>(Wr);
    for (int i = tid; i < 128 * 64; i += 256) {
        int k = i >> 6, q = i & 63;
        float4 v = (q < 32) ? Wl4[k * 32 + q] : Wr4[k * 32 + (q - 32)];
        uint4 w = make_uint4(f2tf(v.x), f2tf(v.y), f2tf(v.z), f2tf(v.w));
        *reinterpret_cast<uint4*>(&Ws[k * WS_STRIDE + q * 4]) = w;
    }

    const int warp = tid >> 5, lane = tid & 31;
    const int g  = lane >> 2;
    const int tk = lane & 3;

    __syncthreads();

    for (int tile = blockIdx.x; tile < ntiles; tile += gridDim.x) {
        #pragma unroll
        for (int j = 0; j < 16; j++) {
            int id = tid + j * 256;
            int r = id >> 5, q = id & 31;
            int grow = tile * 128 + r;
            if (grow < n)
                cp_async16(&xs[r * XS_STRIDE + q * 4],
                           x + (size_t)grow * F + q * 4);
        }
        asm volatile("cp.async.commit_group;");
        asm volatile("cp.async.wait_group 0;");
        __syncthreads();

        const int row0 = tile * 128 + warp * 16 + g;
        const int row1 = row0 + 8;
        const bool r0ok = row0 < n, r1ok = row1 < n;

        float c[32][4];
        #pragma unroll
        for (int t = 0; t < 32; t++) {
            c[t][0] = 0.f; c[t][1] = 0.f; c[t][2] = 0.f; c[t][3] = 0.f;
        }

        const float* x0s = xs + (warp * 16 + g) * XS_STRIDE;
        const float* x1s = x0s + 8 * XS_STRIDE;

        #pragma unroll
        for (int ks = 0; ks < 16; ks++) {
            const int kb = ks * 8;
            unsigned a0 = __float_as_uint(x0s[kb + tk]);
            unsigned a1 = __float_as_uint(x1s[kb + tk]);
            unsigned a2 = __float_as_uint(x0s[kb + tk + 4]);
            unsigned a3 = __float_as_uint(x1s[kb + tk + 4]);
            const unsigned* ws0 = Ws + (kb + tk) * WS_STRIDE + g;
            const unsigned* ws1 = ws0 + 4 * WS_STRIDE;
            #pragma unroll
            for (int nt = 0; nt < 32; nt++) {
                unsigned b0 = ws0[nt * 8];
                unsigned b1 = ws1[nt * 8];
                mma_tf32(c[nt], a0, a1, a2, a3, b0, b1);
            }
        }

        #pragma unroll
        for (int nt = 0; nt < 32; nt++) {
            int col = nt * 8 + tk * 2;
            bool isL = (col < 128);
            int lc = isL ? col : col - 128;
            float b0 = __ldg((isL ? bl : br) + lc);
            float b1 = __ldg((isL ? bl : br) + lc + 1);
            __nv_bfloat162* dst = isL ? g_xlb : g_xrb;
            if (r0ok) {
                __nv_bfloat162 h;
                h.x = __float2bfloat16(c[nt][0] + b0);
                h.y = __float2bfloat16(c[nt][1] + b1);
                dst[(size_t)row0 * 64 + (lc >> 1)] = h;
            }
            if (r1ok) {
                __nv_bfloat162 h;
                h.x = __float2bfloat16(c[nt][2] + b0);
                h.y = __float2bfloat16(c[nt][3] + b1);
                dst[(size_t)row1 * 64 + (lc >> 1)] = h;
            }
        }
        __syncthreads();
    }
}

// ---------------- pass 1: logits + exp + denom (2 edges per half-warp) ------
template<bool PACK16>
__global__ void __launch_bounds__(256) edge_pass1(
    const float* __restrict__ att, int total)
{
    const int lane = threadIdx.x & 31;
    const int sub  = lane & 15;
    const int half = lane >> 4;
    const int warp   = (blockIdx.x * blockDim.x + threadIdx.x) >> 5;
    const int nwarps = (gridDim.x * blockDim.x) >> 5;

    const float4 a0 = reinterpret_cast<const float4*>(att)[sub * 2];
    const float4 a1 = reinterpret_cast<const float4*>(att)[sub * 2 + 1];
    const __nv_bfloat162 at0 = __floats2bfloat162_rn(a0.x, a0.y);
    const __nv_bfloat162 at1 = __floats2bfloat162_rn(a0.z, a0.w);
    const __nv_bfloat162 at2 = __floats2bfloat162_rn(a1.x, a1.y);
    const __nv_bfloat162 at3 = __floats2bfloat162_rn(a1.z, a1.w);
    const __nv_bfloat162 c02 = __float2bfloat162_rn(0.2f);

    const uint4* xl4 = reinterpret_cast<const uint4*>(g_xlb);
    const uint4* xr4 = reinterpret_cast<const uint4*>(g_xrb);
    const ushort2* ep = reinterpret_cast<const ushort2*>(g_edge);

    for (int base = warp * 4; base < total; base += nwarps * 4) {
        const int e0 = base + half * 2;
        const int e1 = e0 + 1;
        const bool ok0 = e0 < total, ok1 = e1 < total;

        int s0 = 0, d0 = 0, s1 = 0, d1 = 0;
        if (PACK16) {
            if (ok1) {
                uint2 m = *reinterpret_cast<const uint2*>(&ep[e0]);
                s0 = m.x & 0xffffu; d0 = m.x >> 16;
                s1 = m.y & 0xffffu; d1 = m.y >> 16;
            } else if (ok0) {
                ushort2 m0 = ep[e0]; s0 = m0.x; d0 = m0.y;
            }
        } else {
            if (ok0) { int2 m0 = g_edge[e0]; s0 = m0.x; d0 = m0.y; }
            if (ok1) { int2 m1 = g_edge[e1]; s1 = m1.x; d1 = m1.y; }
        }

        uint4 up0 = xl4[(unsigned)s0 * 16u + sub];
        uint4 vp0 = xr4[(unsigned)d0 * 16u + sub];
        uint4 up1 = xl4[(unsigned)s1 * 16u + sub];
        uint4 vp1 = xr4[(unsigned)d1 * 16u + sub];

        __nv_bfloat162 acc0 = __float2bfloat162_rn(0.f);
        __nv_bfloat162 acc1 = __float2bfloat162_rn(0.f);
        __nv_bfloat162 z;
        z = __hadd2(*(__nv_bfloat162*)&up0.x, *(__nv_bfloat162*)&vp0.x);
        z = __hmax2(z, __hmul2(z, c02)); acc0 = __hfma2(at0, z, acc0);
        z = __hadd2(*(__nv_bfloat162*)&up0.y, *(__nv_bfloat162*)&vp0.y);
        z = __hmax2(z, __hmul2(z, c02)); acc0 = __hfma2(at1, z, acc0);
        z = __hadd2(*(__nv_bfloat162*)&up0.z, *(__nv_bfloat162*)&vp0.z);
        z = __hmax2(z, __hmul2(z, c02)); acc0 = __hfma2(at2, z, acc0);
        z = __hadd2(*(__nv_bfloat162*)&up0.w, *(__nv_bfloat162*)&vp0.w);
        z = __hmax2(z, __hmul2(z, c02)); acc0 = __hfma2(at3, z, acc0);

        z = __hadd2(*(__nv_bfloat162*)&up1.x, *(__nv_bfloat162*)&vp1.x);
        z = __hmax2(z, __hmul2(z, c02)); acc1 = __hfma2(at0, z, acc1);
        z = __hadd2(*(__nv_bfloat162*)&up1.y, *(__nv_bfloat162*)&vp1.y);
        z = __hmax2(z, __hmul2(z, c02)); acc1 = __hfma2(at1, z, acc1);
        z = __hadd2(*(__nv_bfloat162*)&up1.z, *(__nv_bfloat162*)&vp1.z);
        z = __hmax2(z, __hmul2(z, c02)); acc1 = __hfma2(at2, z, acc1);
        z = __hadd2(*(__nv_bfloat162*)&up1.w, *(__nv_bfloat162*)&vp1.w);
        z = __hmax2(z, __hmul2(z, c02)); acc1 = __hfma2(at3, z, acc1);

        float2 f0 = __bfloat1622float2(acc0);
        float2 f1 = __bfloat1622float2(acc1);
        float sum0 = f0.x + f0.y;
        float sum1 = f1.x + f1.y;

        #pragma unroll
        for (int off = 8; off > 0; off >>= 1) {
            sum0 += __shfl_xor_sync(0xffffffffu, sum0, off);
            sum1 += __shfl_xor_sync(0xffffffffu, sum1, off);
        }

        if (sub == 0) {
            float p0 = __expf(fminf(fmaxf(sum0, -60.f), 60.f));
            float p1 = __expf(fminf(fmaxf(sum1, -60.f), 60.f));
            if (ok1) {
                *reinterpret_cast<float2*>(&g_p[e0]) = make_float2(p0, p1);
                atomicAdd(&g_denom[d0], p0);
                atomicAdd(&g_denom[d1], p1);
            } else if (ok0) {
                g_p[e0] = p0;
                atomicAdd(&g_denom[d0], p0);
            }
        }
    }
}

// ---------------- pass 2: coef[src] += p / denom[dst] (scalar, no features) -
template<bool PACK16>
__global__ void __launch_bounds__(256) edge_pass2(int total) {
    const int i = blockIdx.x * blockDim.x + threadIdx.x;
    const int e0 = i * 2, e1 = e0 + 1;
    if (e0 >= total) return;
    const ushort2* ep = reinterpret_cast<const ushort2*>(g_edge);

    int s0, d0, s1 = 0, d1 = 0;
    bool ok1 = e1 < total;
    if (PACK16) {
        if (ok1) {
            uint2 m = *reinterpret_cast<const uint2*>(&ep[e0]);
            s0 = m.x & 0xffffu; d0 = m.x >> 16;
            s1 = m.y & 0xffffu; d1 = m.y >> 16;
        } else {
            ushort2 m0 = ep[e0]; s0 = m0.x; d0 = m0.y;
        }
    } else {
        int2 m0 = g_edge[e0]; s0 = m0.x; d0 = m0.y;
        if (ok1) { int2 m1 = g_edge[e1]; s1 = m1.x; d1 = m1.y; }
    }

    if (ok1) {
        float2 pv = *reinterpret_cast<const float2*>(&g_p[e0]);
        float w0 = __fdividef(pv.x, g_denom[d0]);
        float w1 = __fdividef(pv.y, g_denom[d1]);
        atomicAdd(&g_coef[s0], w0);
        atomicAdd(&g_coef[s1], w1);
    } else {
        float w0 = __fdividef(g_p[e0], g_denom[d0]);
        atomicAdd(&g_coef[s0], w0);
    }
}

// ---------------- pass 3: dense acc = sum_j coef[j] * xl[j] + finalize ------
__global__ void __launch_bounds__(256) node_sum(
    int nN,
    const float* __restrict__ bias1,
    const float* __restrict__ gamma, const float* __restrict__ beta,
    const float* __restrict__ mean,  const float* __restrict__ var,
    const float* __restrict__ Wc,    const float* __restrict__ bc,
    float* __restrict__ out)
{
    __shared__ float sacc[F];
    __shared__ int s_last;
    const int tid = threadIdx.x;
    if (tid < F) sacc[tid] = 0.f;
    __syncthreads();

    const int lane = tid & 31;
    const int sub  = lane & 15;
    const int half = lane >> 4;
    const int warp   = (blockIdx.x * blockDim.x + tid) >> 5;
    const int nwarps = (gridDim.x * blockDim.x) >> 5;
    const uint4* xl4 = reinterpret_cast<const uint4*>(g_xlb);

    float acc[8];
    #pragma unroll
    for (int k = 0; k < 8; k++) acc[k] = 0.f;

    // each half-warp: one node per iter; 2 nodes per warp per iter
    for (int j = warp * 2 + half; j < nN; j += nwarps * 2) {
        float w = g_coef[j];
        uint4 up = xl4[(unsigned)j * 16u + sub];
        float2 f0 = __bfloat1622float2(*(__nv_bfloat162*)&up.x);
        float2 f1 = __bfloat1622float2(*(__nv_bfloat162*)&up.y);
        float2 f2 = __bfloat1622float2(*(__nv_bfloat162*)&up.z);
        float2 f3 = __bfloat1622float2(*(__nv_bfloat162*)&up.w);
        acc[0] += w * f0.x; acc[1] += w * f0.y;
        acc[2] += w * f1.x; acc[3] += w * f1.y;
        acc[4] += w * f2.x; acc[5] += w * f2.y;
        acc[6] += w * f3.x; acc[7] += w * f3.y;
    }

    #pragma unroll
    for (int k = 0; k < 8; k++)
        acc[k] += __shfl_xor_sync(0xffffffffu, acc[k], 16);
    if (half == 0) {
        #pragma unroll
        for (int k = 0; k < 8; k++)
            atomicAdd(&sacc[sub * 8 + k], acc[k]);
    }
    __syncthreads();
    if (tid < F) atomicAdd(&g_acc[tid], sacc[tid]);

    // ---- last block finalizes ----
    __syncthreads();
    if (tid == 0) {
        __threadfence();
        unsigned v = atomicAdd(&g_done, 1u);
        s_last = (v == gridDim.x - 1) ? 1 : 0;
    }
    __syncthreads();
    if (!s_last) return;

    __shared__ float sg[F];
    __shared__ float sl[5];
    if (tid < F) {
        float gv = atomicAdd(&g_acc[tid], 0.f);   // coherent read
        gv = gv / (float)nN + bias1[tid];
        gv = (gv - mean[tid]) * rsqrtf(var[tid] + 1e-5f) * gamma[tid] + beta[tid];
        sg[tid] = gv;
    }
    __syncthreads();
    if (tid < 5) {
        float s = bc[tid];
        #pragma unroll 8
        for (int k = 0; k < F; k++) s += sg[k] * Wc[k * 5 + tid];
        sl[tid] = s;
    }
    __syncthreads();
    if (tid == 0) {
        float mx = sl[0];
        #pragma unroll
        for (int c = 1; c < 5; c++) mx = fmaxf(mx, sl[c]);
        float e[5], sum = 0.f;
        #pragma unroll
        for (int c = 0; c < 5; c++) { e[c] = expf(sl[c] - mx); sum += e[c]; }
        #pragma unroll
        for (int c = 0; c < 5; c++) out[c] = e[c] / sum;
    }
}

// ---------------- launch ----------------
extern "C" void kernel_launch(void* const* d_in, const int* in_sizes, int n_in,
                              void* d_out, int out_size)
{
    const float* x     = (const float*)d_in[0];
    const void*  ei    = d_in[1];
    const float* Wl    = (const float*)d_in[2];
    const float* bl    = (const float*)d_in[3];
    const float* Wr    = (const float*)d_in[4];
    const float* br    = (const float*)d_in[5];
    const float* att   = (const float*)d_in[6];
    const float* bias1 = (const float*)d_in[7];
    const float* gamma = (const float*)d_in[8];
    const float* beta  = (const float*)d_in[9];
    const float* mean  = (const float*)d_in[10];
    const float* var   = (const float*)d_in[11];
    const float* Wc    = (const float*)d_in[12];
    const float* bc    = (const float*)d_in[13];
    float* out = (float*)d_out;

    const int nN = in_sizes[0] / F;
    const int nE = in_sizes[1] / 2;
    const int total = nE + nN;
    const int ntiles = (nN + 127) / 128;
    const int pack16 = (nN <= 65536) ? 1 : 0;

    static int smem_set = 0;
    if (!smem_set) {
        cudaFuncSetAttribute(gemm_tf32,
            cudaFuncAttributeMaxDynamicSharedMemorySize, GEMM_SMEM);
        smem_set = 1;
    }

    convert_edges<<<(total + 255) / 256, 256>>>(ei, nE, nN, pack16);
    gemm_tf32<<<GEMM_GRID, 256, GEMM_SMEM>>>(x, Wl, bl, Wr, br, nN, ntiles);
    const int p2blocks = (total / 2 + 256) / 256;
    if (pack16) {
        edge_pass1<true><<<2368, 256>>>(att, total);
        edge_pass2<true><<<p2blocks, 256>>>(total);
    } else {
        edge_pass1<false><<<2368, 256>>>(att, total);
        edge_pass2<false><<<p2blocks, 256>>>(total);
    }
    node_sum<<<592, 256>>>(nN, bias1, gamma, beta, mean, var, Wc, bc, out);
}